// round 1
// baseline (speedup 1.0000x reference)
#include <cuda_runtime.h>

#define HID      512
#define NOBJ     8192
#define NREL     32768
#define POOL     4096
#define NRELCLS  51
#define NOBJCLS  151

__device__ float g_edge_rep[NOBJ * 2 * HID];   // [8192 x 1024] fp32 scratch (32 MB)

extern __shared__ float smem[];

// ---------------------------------------------------------------------------
// Kernel 1: edge_rep = relu(edge_ctx[8192,512] @ W_post_emb[512,1024] + b)
// ---------------------------------------------------------------------------
__global__ __launch_bounds__(256, 2) void k_gemm1(
    const float* __restrict__ A,
    const float* __restrict__ B,
    const float* __restrict__ bias)
{
    float* As = smem;            // [64][68]
    float* Bs = smem + 64 * 68;  // [64][128]

    const int t  = threadIdx.x;
    const int tx = t & 31;
    const int ty = t >> 5;
    const int m0 = blockIdx.x * 64;
    const int n0 = blockIdx.y * 128;

    float y[8][4];
#pragma unroll
    for (int i = 0; i < 8; i++)
#pragma unroll
        for (int j = 0; j < 4; j++) y[i][j] = 0.f;

    for (int kt = 0; kt < HID / 64; kt++) {
#pragma unroll
        for (int i = 0; i < 4; i++) {
            int v = t + i * 256;
            int row = v >> 4, cv = v & 15;
            *(float4*)&As[row * 68 + cv * 4] =
                *(const float4*)&A[(size_t)(m0 + row) * HID + kt * 64 + cv * 4];
        }
#pragma unroll
        for (int i = 0; i < 8; i++) {
            int v = t + i * 256;
            int k = v >> 5, nv = v & 31;
            *(float4*)&Bs[k * 128 + nv * 4] =
                *(const float4*)&B[(size_t)(kt * 64 + k) * 1024 + n0 + nv * 4];
        }
        __syncthreads();

#pragma unroll
        for (int kk = 0; kk < 64; kk += 4) {
            float4 b0 = *(float4*)&Bs[(kk + 0) * 128 + tx * 4];
            float4 b1 = *(float4*)&Bs[(kk + 1) * 128 + tx * 4];
            float4 b2 = *(float4*)&Bs[(kk + 2) * 128 + tx * 4];
            float4 b3 = *(float4*)&Bs[(kk + 3) * 128 + tx * 4];
#pragma unroll
            for (int i = 0; i < 8; i++) {
                float4 a = *(float4*)&As[(ty * 8 + i) * 68 + kk];
                y[i][0] += a.x * b0.x; y[i][1] += a.x * b0.y; y[i][2] += a.x * b0.z; y[i][3] += a.x * b0.w;
                y[i][0] += a.y * b1.x; y[i][1] += a.y * b1.y; y[i][2] += a.y * b1.z; y[i][3] += a.y * b1.w;
                y[i][0] += a.z * b2.x; y[i][1] += a.z * b2.y; y[i][2] += a.z * b2.z; y[i][3] += a.z * b2.w;
                y[i][0] += a.w * b3.x; y[i][1] += a.w * b3.y; y[i][2] += a.w * b3.z; y[i][3] += a.w * b3.w;
            }
        }
        __syncthreads();
    }

    float4 bb = *(const float4*)&bias[n0 + tx * 4];
#pragma unroll
    for (int i = 0; i < 8; i++) {
        float4 o;
        o.x = fmaxf(y[i][0] + bb.x, 0.f);
        o.y = fmaxf(y[i][1] + bb.y, 0.f);
        o.z = fmaxf(y[i][2] + bb.z, 0.f);
        o.w = fmaxf(y[i][3] + bb.w, 0.f);
        *(float4*)&g_edge_rep[(size_t)(m0 + ty * 8 + i) * 1024 + n0 + tx * 4] = o;
    }
}

// ---------------------------------------------------------------------------
// Kernel 2 (fused GEMM2 -> *union -> GEMM3 -> +freq)
// ---------------------------------------------------------------------------
__global__ __launch_bounds__(256, 2) void k_fused(
    const float* __restrict__ Wcat,
    const float* __restrict__ bcat,
    const float* __restrict__ unionf,
    const int*   __restrict__ pairs,
    const int*   __restrict__ obj_preds,
    const float* __restrict__ Wctx,
    const float* __restrict__ bctx,
    const float* __restrict__ freq,
    float*       __restrict__ out)
{
    float* As = smem;                       // [64][68]   = 4352 floats
    float* BZ = smem + 4352;                // Bs [64][128]=8192 / z [128][65]=8320
    float* Ws = smem + 4352 + 8320;         // [128][64] padded-group layout
    int*   p0s = (int*)(smem + 4352 + 8320 + 8192);
    int*   p1s = p0s + 64;

    const int t  = threadIdx.x;
    const int tx = t & 31;
    const int ty = t >> 5;
    const int r0 = blockIdx.x * 64;

    if (t < 64) {
        p0s[t] = pairs[(size_t)(r0 + t) * 2 + 0];
        p1s[t] = pairs[(size_t)(r0 + t) * 2 + 1];
    }
    __syncthreads();

    const int m  = t & 63;
    const int g  = t >> 6;
    const int c0 = g * 13;                 // true output column base
    const int nc = (g == 3) ? 12 : 13;
    float acc[13];
#pragma unroll
    for (int j = 0; j < 13; j++) acc[j] = 0.f;

    for (int nch = 0; nch < POOL / 128; nch++) {
        const int n0 = nch * 128;

        float y[8][4];
#pragma unroll
        for (int i = 0; i < 8; i++)
#pragma unroll
            for (int j = 0; j < 4; j++) y[i][j] = 0.f;

        for (int kt = 0; kt < 1024 / 64; kt++) {
#pragma unroll
            for (int i = 0; i < 4; i++) {
                int v = t + i * 256;
                int row = v >> 4, cv = v & 15;
                int src = (kt < 8) ? p0s[row] : p1s[row];
                *(float4*)&As[row * 68 + cv * 4] =
                    *(const float4*)&g_edge_rep[(size_t)src * 1024 + kt * 64 + cv * 4];
            }
#pragma unroll
            for (int i = 0; i < 8; i++) {
                int v = t + i * 256;
                int k = v >> 5, nv = v & 31;
                *(float4*)&BZ[k * 128 + nv * 4] =
                    *(const float4*)&Wcat[(size_t)(kt * 64 + k) * POOL + n0 + nv * 4];
            }
            __syncthreads();

#pragma unroll
            for (int kk = 0; kk < 64; kk += 4) {
                float4 b0 = *(float4*)&BZ[(kk + 0) * 128 + tx * 4];
                float4 b1 = *(float4*)&BZ[(kk + 1) * 128 + tx * 4];
                float4 b2 = *(float4*)&BZ[(kk + 2) * 128 + tx * 4];
                float4 b3 = *(float4*)&BZ[(kk + 3) * 128 + tx * 4];
#pragma unroll
                for (int i = 0; i < 8; i++) {
                    float4 a = *(float4*)&As[(ty * 8 + i) * 68 + kk];
                    y[i][0] += a.x * b0.x; y[i][1] += a.x * b0.y; y[i][2] += a.x * b0.z; y[i][3] += a.x * b0.w;
                    y[i][0] += a.y * b1.x; y[i][1] += a.y * b1.y; y[i][2] += a.y * b1.z; y[i][3] += a.y * b1.w;
                    y[i][0] += a.z * b2.x; y[i][1] += a.z * b2.y; y[i][2] += a.z * b2.z; y[i][3] += a.z * b2.w;
                    y[i][0] += a.w * b3.x; y[i][1] += a.w * b3.y; y[i][2] += a.w * b3.z; y[i][3] += a.w * b3.w;
                }
            }
            __syncthreads();
        }

        // z = (y + b_post_cat) * union  -> n-major smem [128][65]
        {
            float4 bb = *(const float4*)&bcat[n0 + tx * 4];
#pragma unroll
            for (int i = 0; i < 8; i++) {
                int row  = r0 + ty * 8 + i;
                int mloc = ty * 8 + i;
                float4 u = *(const float4*)&unionf[(size_t)row * POOL + n0 + tx * 4];
                BZ[(tx * 4 + 0) * 65 + mloc] = (y[i][0] + bb.x) * u.x;
                BZ[(tx * 4 + 1) * 65 + mloc] = (y[i][1] + bb.y) * u.y;
                BZ[(tx * 4 + 2) * 65 + mloc] = (y[i][2] + bb.z) * u.z;
                BZ[(tx * 4 + 3) * 65 + mloc] = (y[i][3] + bb.w) * u.w;
            }
        }
        // W_ctx chunk: remap column c -> padded offset (c/13)*16 + (c%13)
        // so each group's 13 columns are 16B-aligned at g*16.
        for (int idx = t; idx < 128 * 64; idx += 256) {
            int n = idx >> 6, pc = idx & 63;
            int grp = pc >> 4, off = pc & 15;
            float v = 0.f;
            int c = grp * 13 + off;
            if (off < 13 && c < NRELCLS)
                v = Wctx[(size_t)(n0 + n) * NRELCLS + c];
            Ws[idx] = v;
        }
        __syncthreads();

        const int cbase = g * 16;
#pragma unroll 4
        for (int n = 0; n < 128; n++) {
            float zv = BZ[n * 65 + m];
            float4 w0 = *(float4*)&Ws[n * 64 + cbase + 0];
            float4 w1 = *(float4*)&Ws[n * 64 + cbase + 4];
            float4 w2 = *(float4*)&Ws[n * 64 + cbase + 8];
            float4 w3 = *(float4*)&Ws[n * 64 + cbase + 12];
            acc[0]  += zv * w0.x;  acc[1]  += zv * w0.y;  acc[2]  += zv * w0.z;  acc[3]  += zv * w0.w;
            acc[4]  += zv * w1.x;  acc[5]  += zv * w1.y;  acc[6]  += zv * w1.z;  acc[7]  += zv * w1.w;
            acc[8]  += zv * w2.x;  acc[9]  += zv * w2.y;  acc[10] += zv * w2.z;  acc[11] += zv * w2.w;
            acc[12] += zv * w3.x;
        }
        __syncthreads();
    }

    const int p0 = p0s[m];
    const int p1 = p1s[m];
    const int pidx = obj_preds[p0] * NOBJCLS + obj_preds[p1];
#pragma unroll
    for (int j = 0; j < 13; j++) {
        if (j < nc) {
            out[(size_t)(r0 + m) * NRELCLS + c0 + j] =
                acc[j] + bctx[c0 + j] + freq[(size_t)pidx * NRELCLS + c0 + j];
        }
    }
}

extern "C" void kernel_launch(void* const* d_in, const int* in_sizes, int n_in,
                              void* d_out, int out_size)
{
    const float* edge_ctx   = (const float*)d_in[0];
    const float* unionf     = (const float*)d_in[1];
    const int*   pairs      = (const int*)  d_in[2];
    const int*   obj_preds  = (const int*)  d_in[3];
    const float* W_post_emb = (const float*)d_in[4];
    const float* b_post_emb = (const float*)d_in[5];
    const float* W_post_cat = (const float*)d_in[6];
    const float* b_post_cat = (const float*)d_in[7];
    const float* W_ctx      = (const float*)d_in[8];
    const float* b_ctx      = (const float*)d_in[9];
    const float* freq       = (const float*)d_in[10];
    float* out = (float*)d_out;

    const int SMEM1 = (64 * 68 + 64 * 128) * 4;               // 50176 B
    const int SMEM2 = (4352 + 8320 + 8192) * 4 + 128 * 4;     // 83968 B

    cudaFuncSetAttribute(k_gemm1, cudaFuncAttributeMaxDynamicSharedMemorySize, SMEM1);
    cudaFuncSetAttribute(k_fused, cudaFuncAttributeMaxDynamicSharedMemorySize, SMEM2);

    k_gemm1<<<dim3(NOBJ / 64, 1024 / 128), 256, SMEM1>>>(edge_ctx, W_post_emb, b_post_emb);
    k_fused<<<NREL / 64, 256, SMEM2>>>(W_post_cat, b_post_cat, unionf, pairs, obj_preds,
                                       W_ctx, b_ctx, freq, out);
}

// round 3
// speedup vs baseline: 2.7943x; 2.7943x over previous
#include <cuda_runtime.h>
#include <cuda_fp16.h>
#include <cstdint>

#define HID      512
#define NOBJ     8192
#define NREL     32768
#define POOL     4096
#define NRELCLS  51
#define NOBJCLS  151

// -------------------- device scratch --------------------
__device__ __align__(256) __half g_edge_hi[NOBJ * 1024];
__device__ __align__(256) __half g_edge_lo[NOBJ * 1024];
__device__ __align__(256) __half g_wcatT[POOL * 1024];   // [n][k] fp16 (B col layout)
__device__ __align__(256) __half g_wctxT[64 * POOL];     // [cls pad64][k] fp16

// -------------------- helpers --------------------
__device__ __forceinline__ uint32_t smem_u32(const void* p) {
    uint32_t a;
    asm("{ .reg .u64 t; cvta.to.shared.u64 t, %1; cvt.u32.u64 %0, t; }" : "=r"(a) : "l"(p));
    return a;
}

#define CP16(d, s)   asm volatile("cp.async.cg.shared.global [%0], [%1], 16;" :: "r"(d), "l"(s) : "memory")
#define CP_COMMIT()  asm volatile("cp.async.commit_group;" ::: "memory")
#define WAITG(n)     asm volatile("cp.async.wait_group %0;" :: "n"(n) : "memory")

__device__ __forceinline__ void ldsm4(uint32_t* r, uint32_t a) {
    asm volatile("ldmatrix.sync.aligned.m8n8.x4.shared.b16 {%0,%1,%2,%3}, [%4];"
                 : "=r"(r[0]), "=r"(r[1]), "=r"(r[2]), "=r"(r[3]) : "r"(a));
}
__device__ __forceinline__ void mma16816(float* d, const uint32_t* a, uint32_t b0, uint32_t b1) {
    asm volatile(
        "mma.sync.aligned.m16n8k16.row.col.f32.f16.f16.f32 "
        "{%0,%1,%2,%3}, {%4,%5,%6,%7}, {%8,%9}, {%0,%1,%2,%3};"
        : "+f"(d[0]), "+f"(d[1]), "+f"(d[2]), "+f"(d[3])
        : "r"(a[0]), "r"(a[1]), "r"(a[2]), "r"(a[3]), "r"(b0), "r"(b1));
}
__device__ __forceinline__ uint32_t packh(float e0, float e1) {
    uint32_t r;
    asm("cvt.rn.f16x2.f32 %0, %1, %2;" : "=r"(r) : "f"(e1), "f"(e0));  // low = e0
    return r;
}

// -------------------- smem layout (bytes) --------------------
#define STAGE    49152
#define OFF_AHI  0
#define OFF_ALO  16384
#define OFF_BW   32768
#define ZOFF     98304           // 4 tiles of 16384: (sub*2 + half)
#define WCOFF    163840          // 2 x 8192
#define P0OFF    180224
#define P1OFF    180736
#define OPOFF    181248
#define SMEM_FUSED 181760

// ===========================================================================
// Prep: W_post_cat [1024,4096] fp32 -> g_wcatT [4096][1024] fp16 (transposed)
// ===========================================================================
__global__ void k_wcat_prep(const float* __restrict__ src) {
    __shared__ float tile[32][33];
    int tx = threadIdx.x, ty = threadIdx.y;
    int c0 = blockIdx.x * 32, r0 = blockIdx.y * 32;
    for (int i = ty; i < 32; i += 8)
        tile[i][tx] = src[(size_t)(r0 + i) * POOL + c0 + tx];
    __syncthreads();
    for (int i = ty; i < 32; i += 8)
        g_wcatT[(size_t)(c0 + i) * 1024 + r0 + tx] = __float2half_rn(tile[tx][i]);
}

// Prep: g_wctxT[c][k] = (c < 51) ? W_ctx[k][c] : 0
__global__ void k_wctx_prep(const float* __restrict__ Wctx) {
    int idx = blockIdx.x * 256 + threadIdx.x;   // 64*4096
    int c = idx >> 12, k = idx & 4095;
    float v = (c < NRELCLS) ? Wctx[(size_t)k * NRELCLS + c] : 0.f;
    g_wctxT[idx] = __float2half_rn(v);
}

// ===========================================================================
// GEMM1 (FFMA fp32): edge_rep = relu(edge_ctx @ W_post_emb + b) -> fp16 hi/lo
// ===========================================================================
extern __shared__ float smemf[];
__global__ __launch_bounds__(256, 2) void k_gemm1(
    const float* __restrict__ A, const float* __restrict__ B,
    const float* __restrict__ bias)
{
    float* As = smemf;
    float* Bs = smemf + 64 * 68;
    const int t = threadIdx.x, tx = t & 31, ty = t >> 5;
    const int m0 = blockIdx.x * 64, n0 = blockIdx.y * 128;

    float y[8][4];
#pragma unroll
    for (int i = 0; i < 8; i++)
#pragma unroll
        for (int j = 0; j < 4; j++) y[i][j] = 0.f;

    for (int kt = 0; kt < HID / 64; kt++) {
#pragma unroll
        for (int i = 0; i < 4; i++) {
            int v = t + i * 256, row = v >> 4, cv = v & 15;
            *(float4*)&As[row * 68 + cv * 4] =
                *(const float4*)&A[(size_t)(m0 + row) * HID + kt * 64 + cv * 4];
        }
#pragma unroll
        for (int i = 0; i < 8; i++) {
            int v = t + i * 256, k = v >> 5, nv = v & 31;
            *(float4*)&Bs[k * 128 + nv * 4] =
                *(const float4*)&B[(size_t)(kt * 64 + k) * 1024 + n0 + nv * 4];
        }
        __syncthreads();
#pragma unroll
        for (int kk = 0; kk < 64; kk += 4) {
            float4 b0 = *(float4*)&Bs[(kk + 0) * 128 + tx * 4];
            float4 b1 = *(float4*)&Bs[(kk + 1) * 128 + tx * 4];
            float4 b2 = *(float4*)&Bs[(kk + 2) * 128 + tx * 4];
            float4 b3 = *(float4*)&Bs[(kk + 3) * 128 + tx * 4];
#pragma unroll
            for (int i = 0; i < 8; i++) {
                float4 a = *(float4*)&As[(ty * 8 + i) * 68 + kk];
                y[i][0] += a.x * b0.x; y[i][1] += a.x * b0.y; y[i][2] += a.x * b0.z; y[i][3] += a.x * b0.w;
                y[i][0] += a.y * b1.x; y[i][1] += a.y * b1.y; y[i][2] += a.y * b1.z; y[i][3] += a.y * b1.w;
                y[i][0] += a.z * b2.x; y[i][1] += a.z * b2.y; y[i][2] += a.z * b2.z; y[i][3] += a.z * b2.w;
                y[i][0] += a.w * b3.x; y[i][1] += a.w * b3.y; y[i][2] += a.w * b3.z; y[i][3] += a.w * b3.w;
            }
        }
        __syncthreads();
    }

    float4 bb = *(const float4*)&bias[n0 + tx * 4];
#pragma unroll
    for (int i = 0; i < 8; i++) {
        size_t base = (size_t)(m0 + ty * 8 + i) * 1024 + n0 + tx * 4;
        float v[4] = { fmaxf(y[i][0] + bb.x, 0.f), fmaxf(y[i][1] + bb.y, 0.f),
                       fmaxf(y[i][2] + bb.z, 0.f), fmaxf(y[i][3] + bb.w, 0.f) };
#pragma unroll
        for (int j = 0; j < 4; j++) {
            __half h = __float2half_rn(v[j]);
            g_edge_hi[base + j] = h;
            g_edge_lo[base + j] = __float2half_rn(v[j] - __half2float(h));
        }
    }
}

// ===========================================================================
// Fused mma.sync kernel: GEMM2(gather, fp16 2-pass) -> *union -> GEMM3 -> +freq
// 256 threads (8 warps), M=128 rows/CTA, pool in 32 chunks of 128.
// ===========================================================================
__global__ __launch_bounds__(256, 1) void k_fused_mma(
    const float* __restrict__ bcat,
    const float* __restrict__ unionf,
    const int*   __restrict__ pairs,
    const int*   __restrict__ obj_preds,
    const float* __restrict__ bctx,
    const float* __restrict__ freq,
    float*       __restrict__ out)
{
    extern __shared__ __align__(1024) char smc[];
    const uint32_t sb = smem_u32(smc);
    const int t = threadIdx.x;
    const int lane = t & 31, wid = t >> 5;
    const int wm = wid >> 2, wn = wid & 3;     // GEMM2: 2x4 warps (64m x 32n tiles)
    const int gm = wid >> 1, gn = wid & 1;     // GEMM3: 4x2 warps (32m x 32n tiles)
    const int r0 = blockIdx.x * 128;

    int* p0s = (int*)(smc + P0OFF);
    int* p1s = (int*)(smc + P1OFF);
    int* opx = (int*)(smc + OPOFF);

    if (t < 128) {
        int a = pairs[(size_t)(r0 + t) * 2 + 0];
        int b = pairs[(size_t)(r0 + t) * 2 + 1];
        p0s[t] = a; p1s[t] = b;
        opx[t] = obj_preds[a] * NOBJCLS + obj_preds[b];
    }
    __syncthreads();

    // ---- stage loader (flattened chunk index g = nc*16 + kc over 512) ----
    auto load_stage = [&](int g) {
        const int st = g & 1, kc = g & 15, ncn = g >> 4;
        const uint32_t base = sb + st * STAGE;
        const int row = t >> 1;
        const int j0 = (t & 1) * 4;
        const int src = (kc < 8) ? p0s[row] : p1s[row];
        const __half* gh = &g_edge_hi[(size_t)src * 1024 + kc * 64];
        const __half* gl = &g_edge_lo[(size_t)src * 1024 + kc * 64];
        const __half* gb = &g_wcatT[((size_t)(ncn * 128 + row)) * 1024 + kc * 64];
        const uint32_t rb = row * 128;
        const uint32_t rx = (row & 7) << 4;
#pragma unroll
        for (int i = 0; i < 4; i++) {
            int j = j0 + i;
            uint32_t d = rb + ((j * 16) ^ rx);
            CP16(base + OFF_AHI + d, gh + j * 8);
            CP16(base + OFF_ALO + d, gl + j * 8);
            CP16(base + OFF_BW  + d, gb + j * 8);
        }
    };

    load_stage(0); CP_COMMIT();
    load_stage(1); CP_COMMIT();

    // per-thread fragment addressing constants
    const uint32_t xorv = (lane & 7) << 4;
    const uint32_t khb  = (lane >> 4) * 16;
    const uint32_t arow = (uint32_t)(wm * 64 + (lane & 15)) * 128;
    const uint32_t brow = (uint32_t)(wn * 32 + (lane & 15)) * 128;
    const uint32_t zrow = (uint32_t)(gm * 32 + (lane & 15)) * 128;
    const uint32_t wrow = (uint32_t)(gn * 32 + (lane & 15)) * 128;
    const uint32_t zxor = ((lane >> 2) & 7) << 4;

    float acc3[2][4][4];
#pragma unroll
    for (int a = 0; a < 2; a++)
#pragma unroll
        for (int b = 0; b < 4; b++)
#pragma unroll
            for (int c = 0; c < 4; c++) acc3[a][b][c] = 0.f;

    for (int nc = 0; nc < 32; nc++) {
        const int n0 = nc * 128;
        float acc2[4][4][4];
#pragma unroll
        for (int a = 0; a < 4; a++)
#pragma unroll
            for (int b = 0; b < 4; b++)
#pragma unroll
                for (int c = 0; c < 4; c++) acc2[a][b][c] = 0.f;

        // ---------------- GEMM2 K loop ----------------
        for (int kc = 0; kc < 16; kc++) {
            const int g = nc * 16 + kc;
            if (g == 511) { WAITG(0); } else { WAITG(1); }
            __syncthreads();

            const uint32_t base = sb + (g & 1) * STAGE;
#pragma unroll
            for (int ks = 0; ks < 4; ks++) {
                const uint32_t col = (uint32_t)(ks * 32 + khb) ^ xorv;
                uint32_t bf[2][4];
                ldsm4(bf[0], base + OFF_BW + brow + col);
                ldsm4(bf[1], base + OFF_BW + brow + 16 * 128 + col);
                uint32_t ah[4][4], al[4][4];
#pragma unroll
                for (int mt = 0; mt < 4; mt++) {
                    ldsm4(ah[mt], base + OFF_AHI + arow + mt * 16 * 128 + col);
                    ldsm4(al[mt], base + OFF_ALO + arow + mt * 16 * 128 + col);
                }
#pragma unroll
                for (int mt = 0; mt < 4; mt++)
#pragma unroll
                    for (int nt = 0; nt < 4; nt++) {
                        uint32_t b0 = bf[nt >> 1][nt & 1];
                        uint32_t b1 = bf[nt >> 1][2 + (nt & 1)];
                        mma16816(acc2[mt][nt], ah[mt], b0, b1);
                        mma16816(acc2[mt][nt], al[mt], b0, b1);
                    }
            }
            __syncthreads();
            if (g + 2 < 512) { load_stage(g + 2); CP_COMMIT(); }
        }

        // ---------------- epilogue: z = (acc2 + bcat) * union -> smem fp16 hi/lo ----------------
#pragma unroll
        for (int mt = 0; mt < 4; mt++) {
            const int mloc = wm * 64 + mt * 16 + (lane >> 2);
#pragma unroll
            for (int nt = 0; nt < 4; nt++) {
                const int nl = wn * 32 + nt * 8 + (lane & 3) * 2;
                const int sub = nl >> 6, kl = nl & 63;
                float2 bb = *(const float2*)&bcat[n0 + nl];
                float2 u0 = *(const float2*)&unionf[(size_t)(r0 + mloc) * POOL + n0 + nl];
                float2 u1 = *(const float2*)&unionf[(size_t)(r0 + mloc + 8) * POOL + n0 + nl];
                float z0 = (acc2[mt][nt][0] + bb.x) * u0.x;
                float z1 = (acc2[mt][nt][1] + bb.y) * u0.y;
                float z2 = (acc2[mt][nt][2] + bb.x) * u1.x;
                float z3 = (acc2[mt][nt][3] + bb.y) * u1.y;
                uint32_t h01 = packh(z0, z1), h23 = packh(z2, z3);
                __half2 hh01 = *(__half2*)&h01, hh23 = *(__half2*)&h23;
                uint32_t l01 = packh(z0 - __half2float(hh01.x), z1 - __half2float(hh01.y));
                uint32_t l23 = packh(z2 - __half2float(hh23.x), z3 - __half2float(hh23.y));
                uint32_t d0 = (uint32_t)mloc * 128 + (((uint32_t)kl * 2) ^ zxor);
                uint32_t d1 = d0 + 8 * 128;
                *(uint32_t*)(smc + ZOFF + (sub * 2 + 0) * 16384 + d0) = h01;
                *(uint32_t*)(smc + ZOFF + (sub * 2 + 0) * 16384 + d1) = h23;
                *(uint32_t*)(smc + ZOFF + (sub * 2 + 1) * 16384 + d0) = l01;
                *(uint32_t*)(smc + ZOFF + (sub * 2 + 1) * 16384 + d1) = l23;
            }
        }
        // W_ctx chunk tiles: [64 cls][64 k] x 2 subs
#pragma unroll
        for (int i = 0; i < 4; i++) {
            int idx = t + i * 256;
            int s = idx >> 9, rem = idx & 511, row = rem >> 3, j = rem & 7;
            uint32_t d = (uint32_t)(WCOFF + s * 8192) + (uint32_t)row * 128 +
                         (((uint32_t)j * 16) ^ ((uint32_t)(row & 7) << 4));
            CP16(sb + d, &g_wctxT[(size_t)row * POOL + n0 + s * 64 + j * 8]);
        }
        CP_COMMIT();
        WAITG(0);
        __syncthreads();

        // ---------------- GEMM3 accumulate (persistent acc3) ----------------
#pragma unroll
        for (int s = 0; s < 2; s++) {
#pragma unroll
            for (int ks = 0; ks < 4; ks++) {
                const uint32_t col = (uint32_t)(ks * 32 + khb) ^ xorv;
                uint32_t bf[2][4];
                ldsm4(bf[0], sb + WCOFF + s * 8192 + wrow + col);
                ldsm4(bf[1], sb + WCOFF + s * 8192 + wrow + 16 * 128 + col);
                uint32_t zh[2][4], zl[2][4];
#pragma unroll
                for (int mt = 0; mt < 2; mt++) {
                    ldsm4(zh[mt], sb + ZOFF + (s * 2 + 0) * 16384 + zrow + mt * 16 * 128 + col);
                    ldsm4(zl[mt], sb + ZOFF + (s * 2 + 1) * 16384 + zrow + mt * 16 * 128 + col);
                }
#pragma unroll
                for (int mt = 0; mt < 2; mt++)
#pragma unroll
                    for (int nt = 0; nt < 4; nt++) {
                        uint32_t b0 = bf[nt >> 1][nt & 1];
                        uint32_t b1 = bf[nt >> 1][2 + (nt & 1)];
                        mma16816(acc3[mt][nt], zh[mt], b0, b1);
                        mma16816(acc3[mt][nt], zl[mt], b0, b1);
                    }
            }
        }
        __syncthreads();   // protect z/WC tiles before next chunk's epilogue
    }

    // ---------------- final: out = acc3 + bctx + freq ----------------
#pragma unroll
    for (int mt = 0; mt < 2; mt++) {
        const int m0l = gm * 32 + mt * 16 + (lane >> 2);
#pragma unroll
        for (int r = 0; r < 2; r++) {
            const int m = m0l + r * 8;
            const int pidx = opx[m];
            const float* fr = &freq[(size_t)pidx * NRELCLS];
            float* op = &out[(size_t)(r0 + m) * NRELCLS];
#pragma unroll
            for (int nt = 0; nt < 4; nt++) {
                const int c = gn * 32 + nt * 8 + (lane & 3) * 2;
                if (c < NRELCLS)
                    op[c] = acc3[mt][nt][r * 2 + 0] + bctx[c] + fr[c];
                if (c + 1 < NRELCLS)
                    op[c + 1] = acc3[mt][nt][r * 2 + 1] + bctx[c + 1] + fr[c + 1];
            }
        }
    }
}

// ===========================================================================
extern "C" void kernel_launch(void* const* d_in, const int* in_sizes, int n_in,
                              void* d_out, int out_size)
{
    const float* edge_ctx   = (const float*)d_in[0];
    const float* unionf     = (const float*)d_in[1];
    const int*   pairs      = (const int*)  d_in[2];
    const int*   obj_preds  = (const int*)  d_in[3];
    const float* W_post_emb = (const float*)d_in[4];
    const float* b_post_emb = (const float*)d_in[5];
    const float* W_post_cat = (const float*)d_in[6];
    const float* b_post_cat = (const float*)d_in[7];
    const float* W_ctx      = (const float*)d_in[8];
    const float* b_ctx      = (const float*)d_in[9];
    const float* freq       = (const float*)d_in[10];
    float* out = (float*)d_out;

    const int SMEM1 = (64 * 68 + 64 * 128) * 4;
    cudaFuncSetAttribute(k_gemm1, cudaFuncAttributeMaxDynamicSharedMemorySize, SMEM1);
    cudaFuncSetAttribute(k_fused_mma, cudaFuncAttributeMaxDynamicSharedMemorySize, SMEM_FUSED);

    k_wcat_prep<<<dim3(POOL / 32, 1024 / 32), dim3(32, 8)>>>(W_post_cat);
    k_wctx_prep<<<(64 * POOL) / 256, 256>>>(W_ctx);
    k_gemm1<<<dim3(NOBJ / 64, 1024 / 128), 256, SMEM1>>>(edge_ctx, W_post_emb, b_post_emb);
    k_fused_mma<<<NREL / 128, 256, SMEM_FUSED>>>(b_post_cat, unionf, pairs, obj_preds,
                                                 b_ctx, freq, out);
}

// round 4
// speedup vs baseline: 5.5273x; 1.9781x over previous
#include <cuda_runtime.h>
#include <cuda_fp16.h>
#include <cstdint>

#define HID      512
#define NOBJ     8192
#define NREL     32768
#define POOL     4096
#define NRELCLS  51
#define NOBJCLS  151

// -------------------- device scratch --------------------
__device__ __align__(256) __half g_edge_hi[NOBJ * 1024];
__device__ __align__(256) __half g_wcatT[POOL * 1024];   // [n][k] fp16
__device__ __align__(256) __half g_wctxT[64 * POOL];     // [cls pad64][k] fp16

// -------------------- helpers --------------------
__device__ __forceinline__ uint32_t smem_u32(const void* p) {
    uint32_t a;
    asm("{ .reg .u64 t; cvta.to.shared.u64 t, %1; cvt.u32.u64 %0, t; }" : "=r"(a) : "l"(p));
    return a;
}
#define CP16(d, s)   asm volatile("cp.async.cg.shared.global [%0], [%1], 16;" :: "r"(d), "l"(s) : "memory")
#define CP_COMMIT()  asm volatile("cp.async.commit_group;" ::: "memory")
#define WAITG(n)     asm volatile("cp.async.wait_group %0;" :: "n"(n) : "memory")

__device__ __forceinline__ void ldsm4(uint32_t* r, uint32_t a) {
    asm volatile("ldmatrix.sync.aligned.m8n8.x4.shared.b16 {%0,%1,%2,%3}, [%4];"
                 : "=r"(r[0]), "=r"(r[1]), "=r"(r[2]), "=r"(r[3]) : "r"(a));
}
__device__ __forceinline__ void mma16816(float* d, const uint32_t* a, uint32_t b0, uint32_t b1) {
    asm volatile(
        "mma.sync.aligned.m16n8k16.row.col.f32.f16.f16.f32 "
        "{%0,%1,%2,%3}, {%4,%5,%6,%7}, {%8,%9}, {%0,%1,%2,%3};"
        : "+f"(d[0]), "+f"(d[1]), "+f"(d[2]), "+f"(d[3])
        : "r"(a[0]), "r"(a[1]), "r"(a[2]), "r"(a[3]), "r"(b0), "r"(b1));
}
__device__ __forceinline__ uint32_t packh(float e0, float e1) {
    uint32_t r;
    asm("cvt.rn.f16x2.f32 %0, %1, %2;" : "=r"(r) : "f"(e1), "f"(e0));  // low = e0
    return r;
}

// -------------------- smem layout (bytes) --------------------
#define STAGE    32768
#define OFF_A    0
#define OFF_B    16384
#define ZOFF     65536          // 4 x 16384: (sub*2 + half), sub = k-half, half = hi/lo
#define WCOFF    131072         // 2 x 8192
#define P0OFF    147456
#define P1OFF    147968
#define OPOFF    148480
#define SMEM_FUSED 148992

// ===========================================================================
// Prep: W_post_cat [1024,4096] fp32 -> g_wcatT [4096][1024] fp16 (transposed)
// ===========================================================================
__global__ void k_wcat_prep(const float* __restrict__ src) {
    __shared__ float tile[32][33];
    int tx = threadIdx.x, ty = threadIdx.y;
    int c0 = blockIdx.x * 32, r0 = blockIdx.y * 32;
    for (int i = ty; i < 32; i += 8)
        tile[i][tx] = src[(size_t)(r0 + i) * POOL + c0 + tx];
    __syncthreads();
    for (int i = ty; i < 32; i += 8)
        g_wcatT[(size_t)(c0 + i) * 1024 + r0 + tx] = __float2half_rn(tile[tx][i]);
}

__global__ void k_wctx_prep(const float* __restrict__ Wctx) {
    int idx = blockIdx.x * 256 + threadIdx.x;   // 64*4096
    int c = idx >> 12, k = idx & 4095;
    float v = (c < NRELCLS) ? Wctx[(size_t)k * NRELCLS + c] : 0.f;
    g_wctxT[idx] = __float2half_rn(v);
}

// ===========================================================================
// GEMM1 (FFMA fp32): edge_rep = relu(edge_ctx @ W_post_emb + b) -> fp16
// ===========================================================================
extern __shared__ float smemf[];
__global__ __launch_bounds__(256, 2) void k_gemm1(
    const float* __restrict__ A, const float* __restrict__ B,
    const float* __restrict__ bias)
{
    float* As = smemf;
    float* Bs = smemf + 64 * 68;
    const int t = threadIdx.x, tx = t & 31, ty = t >> 5;
    const int m0 = blockIdx.x * 64, n0 = blockIdx.y * 128;

    float y[8][4];
#pragma unroll
    for (int i = 0; i < 8; i++)
#pragma unroll
        for (int j = 0; j < 4; j++) y[i][j] = 0.f;

    for (int kt = 0; kt < HID / 64; kt++) {
#pragma unroll
        for (int i = 0; i < 4; i++) {
            int v = t + i * 256, row = v >> 4, cv = v & 15;
            *(float4*)&As[row * 68 + cv * 4] =
                *(const float4*)&A[(size_t)(m0 + row) * HID + kt * 64 + cv * 4];
        }
#pragma unroll
        for (int i = 0; i < 8; i++) {
            int v = t + i * 256, k = v >> 5, nv = v & 31;
            *(float4*)&Bs[k * 128 + nv * 4] =
                *(const float4*)&B[(size_t)(kt * 64 + k) * 1024 + n0 + nv * 4];
        }
        __syncthreads();
#pragma unroll
        for (int kk = 0; kk < 64; kk += 4) {
            float4 b0 = *(float4*)&Bs[(kk + 0) * 128 + tx * 4];
            float4 b1 = *(float4*)&Bs[(kk + 1) * 128 + tx * 4];
            float4 b2 = *(float4*)&Bs[(kk + 2) * 128 + tx * 4];
            float4 b3 = *(float4*)&Bs[(kk + 3) * 128 + tx * 4];
#pragma unroll
            for (int i = 0; i < 8; i++) {
                float4 a = *(float4*)&As[(ty * 8 + i) * 68 + kk];
                y[i][0] += a.x * b0.x; y[i][1] += a.x * b0.y; y[i][2] += a.x * b0.z; y[i][3] += a.x * b0.w;
                y[i][0] += a.y * b1.x; y[i][1] += a.y * b1.y; y[i][2] += a.y * b1.z; y[i][3] += a.y * b1.w;
                y[i][0] += a.z * b2.x; y[i][1] += a.z * b2.y; y[i][2] += a.z * b2.z; y[i][3] += a.z * b2.w;
                y[i][0] += a.w * b3.x; y[i][1] += a.w * b3.y; y[i][2] += a.w * b3.z; y[i][3] += a.w * b3.w;
            }
        }
        __syncthreads();
    }

    float4 bb = *(const float4*)&bias[n0 + tx * 4];
#pragma unroll
    for (int i = 0; i < 8; i++) {
        size_t base = (size_t)(m0 + ty * 8 + i) * 1024 + n0 + tx * 4;
        __half2 h01 = __floats2half2_rn(fmaxf(y[i][0] + bb.x, 0.f), fmaxf(y[i][1] + bb.y, 0.f));
        __half2 h23 = __floats2half2_rn(fmaxf(y[i][2] + bb.z, 0.f), fmaxf(y[i][3] + bb.w, 0.f));
        *(__half2*)&g_edge_hi[base + 0] = h01;
        *(__half2*)&g_edge_hi[base + 2] = h23;
    }
}

// ===========================================================================
// Fused: GEMM2 (single-pass fp16) -> *union -> GEMM3 (2-pass split z) -> +freq
// 512 threads (16 warps), M=128 rows/CTA, pool in 32 chunks of 128.
// GEMM2 warps 4x4 (32m x 32n), GEMM3 warps 4x4 (32m x 16n).
// ===========================================================================
__global__ __launch_bounds__(512, 1) void k_fused_mma(
    const float* __restrict__ bcat,
    const float* __restrict__ unionf,
    const int*   __restrict__ pairs,
    const int*   __restrict__ obj_preds,
    const float* __restrict__ bctx,
    const float* __restrict__ freq,
    float*       __restrict__ out)
{
    extern __shared__ __align__(1024) char smc[];
    const uint32_t sb = smem_u32(smc);
    const int t = threadIdx.x;
    const int lane = t & 31, wid = t >> 5;
    const int wm = wid >> 2, wn = wid & 3;     // GEMM2 warp grid
    const int gm = wid >> 2, gn = wid & 3;     // GEMM3 warp grid
    const int r0 = blockIdx.x * 128;

    int* p0s = (int*)(smc + P0OFF);
    int* p1s = (int*)(smc + P1OFF);
    int* opx = (int*)(smc + OPOFF);

    if (t < 128) {
        int a = pairs[(size_t)(r0 + t) * 2 + 0];
        int b = pairs[(size_t)(r0 + t) * 2 + 1];
        p0s[t] = a; p1s[t] = b;
        opx[t] = obj_preds[a] * NOBJCLS + obj_preds[b];
    }
    __syncthreads();

    // ---- stage loader: A tile [128m][64k] gathered, B tile [128n][64k] ----
    auto load_stage = [&](int g) {
        const int st = g & 1, kc = g & 15, ncn = g >> 4;
        const uint32_t base = sb + st * STAGE;
#pragma unroll
        for (int i = 0; i < 2; i++) {
            int idx = t + i * 512;               // 1024 uint4 slots
            int row = idx >> 3, j = idx & 7;
            uint32_t d = (uint32_t)row * 128 + (((uint32_t)j * 16) ^ ((uint32_t)(row & 7) << 4));
            int src = (kc < 8) ? p0s[row] : p1s[row];
            CP16(base + OFF_A + d, &g_edge_hi[(size_t)src * 1024 + kc * 64 + j * 8]);
            CP16(base + OFF_B + d, &g_wcatT[((size_t)(ncn * 128 + row)) * 1024 + kc * 64 + j * 8]);
        }
    };

    load_stage(0); CP_COMMIT();
    load_stage(1); CP_COMMIT();

    // fragment addressing
    const uint32_t xorv = (lane & 7) << 4;
    const uint32_t khb  = (lane >> 4) * 16;
    const uint32_t arow = (uint32_t)(wm * 32 + (lane & 15)) * 128;
    const uint32_t brow = (uint32_t)(wn * 32 + (lane & 15)) * 128;
    const uint32_t zrow = (uint32_t)(gm * 32 + (lane & 15)) * 128;
    const uint32_t wrow = (uint32_t)(gn * 16 + (lane & 15)) * 128;
    const uint32_t zxor = ((lane >> 2) & 7) << 4;

    float acc3[2][2][4];
#pragma unroll
    for (int a = 0; a < 2; a++)
#pragma unroll
        for (int b = 0; b < 2; b++)
#pragma unroll
            for (int c = 0; c < 4; c++) acc3[a][b][c] = 0.f;

    for (int nc = 0; nc < 32; nc++) {
        const int n0 = nc * 128;
        float acc2[2][4][4];
#pragma unroll
        for (int a = 0; a < 2; a++)
#pragma unroll
            for (int b = 0; b < 4; b++)
#pragma unroll
                for (int c = 0; c < 4; c++) acc2[a][b][c] = 0.f;

        // ---------------- GEMM2 K loop (single pass) ----------------
        for (int kc = 0; kc < 16; kc++) {
            const int g = nc * 16 + kc;
            if (g == 511) { WAITG(0); } else { WAITG(1); }
            __syncthreads();

            const uint32_t base = sb + (g & 1) * STAGE;
#pragma unroll
            for (int ks = 0; ks < 4; ks++) {
                const uint32_t col = (uint32_t)(ks * 32 + khb) ^ xorv;
                uint32_t bf[2][4];
                ldsm4(bf[0], base + OFF_B + brow + col);
                ldsm4(bf[1], base + OFF_B + brow + 16 * 128 + col);
                uint32_t ah[2][4];
#pragma unroll
                for (int mt = 0; mt < 2; mt++)
                    ldsm4(ah[mt], base + OFF_A + arow + mt * 16 * 128 + col);
#pragma unroll
                for (int mt = 0; mt < 2; mt++)
#pragma unroll
                    for (int nt = 0; nt < 4; nt++)
                        mma16816(acc2[mt][nt], ah[mt],
                                 bf[nt >> 1][nt & 1], bf[nt >> 1][2 + (nt & 1)]);
            }
            __syncthreads();
            if (g + 2 < 512) { load_stage(g + 2); CP_COMMIT(); }
        }

        // ---------------- epilogue: z = (acc2 + bcat) * union -> smem hi/lo ----------------
#pragma unroll
        for (int mt = 0; mt < 2; mt++) {
            const int mloc = wm * 32 + mt * 16 + (lane >> 2);
#pragma unroll
            for (int nt = 0; nt < 4; nt++) {
                const int nl = wn * 32 + nt * 8 + (lane & 3) * 2;
                const int sub = nl >> 6, kl = nl & 63;
                float2 bb = *(const float2*)&bcat[n0 + nl];
                float2 u0 = *(const float2*)&unionf[(size_t)(r0 + mloc) * POOL + n0 + nl];
                float2 u1 = *(const float2*)&unionf[(size_t)(r0 + mloc + 8) * POOL + n0 + nl];
                float z0 = (acc2[mt][nt][0] + bb.x) * u0.x;
                float z1 = (acc2[mt][nt][1] + bb.y) * u0.y;
                float z2 = (acc2[mt][nt][2] + bb.x) * u1.x;
                float z3 = (acc2[mt][nt][3] + bb.y) * u1.y;
                uint32_t h01 = packh(z0, z1), h23 = packh(z2, z3);
                __half2 hh01 = *(__half2*)&h01, hh23 = *(__half2*)&h23;
                uint32_t l01 = packh(z0 - __half2float(hh01.x), z1 - __half2float(hh01.y));
                uint32_t l23 = packh(z2 - __half2float(hh23.x), z3 - __half2float(hh23.y));
                uint32_t d0 = (uint32_t)mloc * 128 + (((uint32_t)kl * 2) ^ zxor);
                uint32_t d1 = d0 + 8 * 128;
                *(uint32_t*)(smc + ZOFF + (sub * 2 + 0) * 16384 + d0) = h01;
                *(uint32_t*)(smc + ZOFF + (sub * 2 + 0) * 16384 + d1) = h23;
                *(uint32_t*)(smc + ZOFF + (sub * 2 + 1) * 16384 + d0) = l01;
                *(uint32_t*)(smc + ZOFF + (sub * 2 + 1) * 16384 + d1) = l23;
            }
        }
        // W_ctx tiles: 2 subs of [64 cls][64 k]
#pragma unroll
        for (int i = 0; i < 2; i++) {
            int idx = t + i * 512;               // 1024 slots
            int s = idx >> 9, rem = idx & 511, row = rem >> 3, j = rem & 7;
            uint32_t d = (uint32_t)(WCOFF + s * 8192) + (uint32_t)row * 128 +
                         (((uint32_t)j * 16) ^ ((uint32_t)(row & 7) << 4));
            CP16(sb + d, &g_wctxT[(size_t)row * POOL + n0 + s * 64 + j * 8]);
        }
        CP_COMMIT();
        WAITG(0);
        __syncthreads();

        // ---------------- GEMM3 accumulate (2-pass: z_hi + z_lo) ----------------
#pragma unroll
        for (int s = 0; s < 2; s++) {
#pragma unroll
            for (int ks = 0; ks < 4; ks++) {
                const uint32_t col = (uint32_t)(ks * 32 + khb) ^ xorv;
                uint32_t bf[4];
                ldsm4(bf, sb + WCOFF + s * 8192 + wrow + col);
                uint32_t zh[2][4], zl[2][4];
#pragma unroll
                for (int mt = 0; mt < 2; mt++) {
                    ldsm4(zh[mt], sb + ZOFF + (s * 2 + 0) * 16384 + zrow + mt * 16 * 128 + col);
                    ldsm4(zl[mt], sb + ZOFF + (s * 2 + 1) * 16384 + zrow + mt * 16 * 128 + col);
                }
#pragma unroll
                for (int mt = 0; mt < 2; mt++)
#pragma unroll
                    for (int nt = 0; nt < 2; nt++) {
                        mma16816(acc3[mt][nt], zh[mt], bf[nt], bf[2 + nt]);
                        mma16816(acc3[mt][nt], zl[mt], bf[nt], bf[2 + nt]);
                    }
            }
        }
        __syncthreads();   // protect z/WC before next chunk's epilogue
    }

    // ---------------- final: out = acc3 + bctx + freq ----------------
#pragma unroll
    for (int mt = 0; mt < 2; mt++) {
        const int m0l = gm * 32 + mt * 16 + (lane >> 2);
#pragma unroll
        for (int r = 0; r < 2; r++) {
            const int m = m0l + r * 8;
            const int pidx = opx[m];
            const float* fr = &freq[(size_t)pidx * NRELCLS];
            float* op = &out[(size_t)(r0 + m) * NRELCLS];
#pragma unroll
            for (int nt = 0; nt < 2; nt++) {
                const int c = gn * 16 + nt * 8 + (lane & 3) * 2;
                if (c < NRELCLS)
                    op[c] = acc3[mt][nt][r * 2 + 0] + bctx[c] + fr[c];
                if (c + 1 < NRELCLS)
                    op[c + 1] = acc3[mt][nt][r * 2 + 1] + bctx[c + 1] + fr[c + 1];
            }
        }
    }
}

// ===========================================================================
extern "C" void kernel_launch(void* const* d_in, const int* in_sizes, int n_in,
                              void* d_out, int out_size)
{
    const float* edge_ctx   = (const float*)d_in[0];
    const float* unionf     = (const float*)d_in[1];
    const int*   pairs      = (const int*)  d_in[2];
    const int*   obj_preds  = (const int*)  d_in[3];
    const float* W_post_emb = (const float*)d_in[4];
    const float* b_post_emb = (const float*)d_in[5];
    const float* W_post_cat = (const float*)d_in[6];
    const float* b_post_cat = (const float*)d_in[7];
    const float* W_ctx      = (const float*)d_in[8];
    const float* b_ctx      = (const float*)d_in[9];
    const float* freq       = (const float*)d_in[10];
    float* out = (float*)d_out;

    const int SMEM1 = (64 * 68 + 64 * 128) * 4;
    cudaFuncSetAttribute(k_gemm1, cudaFuncAttributeMaxDynamicSharedMemorySize, SMEM1);
    cudaFuncSetAttribute(k_fused_mma, cudaFuncAttributeMaxDynamicSharedMemorySize, SMEM_FUSED);

    k_wcat_prep<<<dim3(POOL / 32, 1024 / 32), dim3(32, 8)>>>(W_post_cat);
    k_wctx_prep<<<(64 * POOL) / 256, 256>>>(W_ctx);
    k_gemm1<<<dim3(NOBJ / 64, 1024 / 128), 256, SMEM1>>>(edge_ctx, W_post_emb, b_post_emb);
    k_fused_mma<<<NREL / 128, 512, SMEM_FUSED>>>(b_post_cat, unionf, pairs, obj_preds,
                                                 b_ctx, freq, out);
}

// round 5
// speedup vs baseline: 6.3095x; 1.1415x over previous
#include <cuda_runtime.h>
#include <cuda_fp16.h>
#include <cstdint>

#define HID      512
#define NOBJ     8192
#define NREL     32768
#define POOL     4096
#define NRELCLS  51
#define NOBJCLS  151

// -------------------- device scratch --------------------
__device__ __align__(256) __half g_edge_hi[NOBJ * 1024];
__device__ __align__(256) __half g_wcatT[POOL * 1024];   // [n][k] fp16
__device__ __align__(256) __half g_wctxT[64 * POOL];     // [cls pad64][k] fp16
__device__ __align__(256) __half g_ec_hi[NOBJ * HID];    // edge_ctx split
__device__ __align__(256) __half g_ec_lo[NOBJ * HID];
__device__ __align__(256) __half g_wembT[1024 * HID];    // [n][k] fp16

// -------------------- helpers --------------------
__device__ __forceinline__ uint32_t smem_u32(const void* p) {
    uint32_t a;
    asm("{ .reg .u64 t; cvta.to.shared.u64 t, %1; cvt.u32.u64 %0, t; }" : "=r"(a) : "l"(p));
    return a;
}
#define CP16(d, s)   asm volatile("cp.async.cg.shared.global [%0], [%1], 16;" :: "r"(d), "l"(s) : "memory")
#define CP_COMMIT()  asm volatile("cp.async.commit_group;" ::: "memory")
#define WAITG(n)     asm volatile("cp.async.wait_group %0;" :: "n"(n) : "memory")

__device__ __forceinline__ void ldsm4(uint32_t* r, uint32_t a) {
    asm volatile("ldmatrix.sync.aligned.m8n8.x4.shared.b16 {%0,%1,%2,%3}, [%4];"
                 : "=r"(r[0]), "=r"(r[1]), "=r"(r[2]), "=r"(r[3]) : "r"(a));
}
__device__ __forceinline__ void mma16816(float* d, const uint32_t* a, uint32_t b0, uint32_t b1) {
    asm volatile(
        "mma.sync.aligned.m16n8k16.row.col.f32.f16.f16.f32 "
        "{%0,%1,%2,%3}, {%4,%5,%6,%7}, {%8,%9}, {%0,%1,%2,%3};"
        : "+f"(d[0]), "+f"(d[1]), "+f"(d[2]), "+f"(d[3])
        : "r"(a[0]), "r"(a[1]), "r"(a[2]), "r"(a[3]), "r"(b0), "r"(b1));
}
__device__ __forceinline__ uint32_t packh(float e0, float e1) {
    uint32_t r;
    asm("cvt.rn.f16x2.f32 %0, %1, %2;" : "=r"(r) : "f"(e1), "f"(e0));  // low = e0
    return r;
}

// -------------------- smem layout: fused kernel (bytes) --------------------
#define STAGE    65536           // A [128m][128k] 32KB + B [128n][128k] 32KB
#define OFF_A    0
#define OFF_B    32768
#define ZOFF     131072          // 2 x 16384: z hi, sub = k-half
#define WCOFF    163840          // 2 x 8192
#define P0OFF    180224
#define P1OFF    180736
#define OPOFF    181248
#define SMEM_FUSED 181760

// -------------------- smem layout: gemm1 kernel --------------------
#define G1STAGE  49152           // Ahi 16K + Alo 16K + B 16K
#define G1_AHI   0
#define G1_ALO   16384
#define G1_B     32768
#define SMEM_G1  98304

// ===========================================================================
// Preps
// ===========================================================================
__global__ void k_ec_prep(const float* __restrict__ src) {
    int idx = blockIdx.x * 256 + threadIdx.x;     // NOBJ*HID / 256 blocks
    float v = src[idx];
    __half h = __float2half_rn(v);
    g_ec_hi[idx] = h;
    g_ec_lo[idx] = __float2half_rn(v - __half2float(h));
}

__global__ void k_wemb_prep(const float* __restrict__ src) {  // [512][1024] -> [1024][512]
    __shared__ float tile[32][33];
    int tx = threadIdx.x, ty = threadIdx.y;
    int c0 = blockIdx.x * 32, r0 = blockIdx.y * 32;
    for (int i = ty; i < 32; i += 8)
        tile[i][tx] = src[(size_t)(r0 + i) * 1024 + c0 + tx];
    __syncthreads();
    for (int i = ty; i < 32; i += 8)
        g_wembT[(size_t)(c0 + i) * HID + r0 + tx] = __float2half_rn(tile[tx][i]);
}

__global__ void k_wcat_prep(const float* __restrict__ src) {  // [1024][4096] -> [4096][1024]
    __shared__ float tile[32][33];
    int tx = threadIdx.x, ty = threadIdx.y;
    int c0 = blockIdx.x * 32, r0 = blockIdx.y * 32;
    for (int i = ty; i < 32; i += 8)
        tile[i][tx] = src[(size_t)(r0 + i) * POOL + c0 + tx];
    __syncthreads();
    for (int i = ty; i < 32; i += 8)
        g_wcatT[(size_t)(c0 + i) * 1024 + r0 + tx] = __float2half_rn(tile[tx][i]);
}

__global__ void k_wctx_prep(const float* __restrict__ Wctx) {
    int idx = blockIdx.x * 256 + threadIdx.x;   // 64*4096
    int c = idx >> 12, k = idx & 4095;
    float v = (c < NRELCLS) ? Wctx[(size_t)k * NRELCLS + c] : 0.f;
    g_wctxT[idx] = __float2half_rn(v);
}

// ===========================================================================
// GEMM1 (mma, 2-pass A): edge_rep = relu(edge_ctx @ W_post_emb + b) -> fp16
// 512 threads, CTA tile 128m x 128n, K=512 in 8 stages of 64.
// ===========================================================================
__global__ __launch_bounds__(512, 1) void k_gemm1_mma(const float* __restrict__ bias)
{
    extern __shared__ __align__(1024) char smc[];
    const uint32_t sb = smem_u32(smc);
    const int t = threadIdx.x;
    const int lane = t & 31, wid = t >> 5;
    const int wm = wid >> 2, wn = wid & 3;
    const int m0 = blockIdx.x * 128, n0 = blockIdx.y * 128;

    auto load_stage = [&](int kc) {
        const uint32_t base = sb + (kc & 1) * G1STAGE;
        // 3 arrays x 1024 uint4 slots = 3072; 6 per thread
#pragma unroll
        for (int i = 0; i < 2; i++) {
            int idx = t + i * 512;                // 1024
            int row = idx >> 3, j = idx & 7;
            uint32_t d = (uint32_t)row * 128 + (((uint32_t)j * 16) ^ ((uint32_t)(row & 7) << 4));
            CP16(base + G1_AHI + d, &g_ec_hi[(size_t)(m0 + row) * HID + kc * 64 + j * 8]);
            CP16(base + G1_ALO + d, &g_ec_lo[(size_t)(m0 + row) * HID + kc * 64 + j * 8]);
            CP16(base + G1_B   + d, &g_wembT[(size_t)(n0 + row) * HID + kc * 64 + j * 8]);
        }
    };
    load_stage(0); CP_COMMIT();
    load_stage(1); CP_COMMIT();

    const uint32_t xorv = (lane & 7) << 4;
    const uint32_t khb  = (lane >> 4) * 16;
    const uint32_t arow = (uint32_t)(wm * 32 + (lane & 15)) * 128;
    const uint32_t brow = (uint32_t)(wn * 32 + (lane & 15)) * 128;

    float acc[2][4][4];
#pragma unroll
    for (int a = 0; a < 2; a++)
#pragma unroll
        for (int b = 0; b < 4; b++)
#pragma unroll
            for (int c = 0; c < 4; c++) acc[a][b][c] = 0.f;

    for (int kc = 0; kc < 8; kc++) {
        if (kc == 7) { WAITG(0); } else { WAITG(1); }
        __syncthreads();
        const uint32_t base = sb + (kc & 1) * G1STAGE;
#pragma unroll
        for (int ks = 0; ks < 4; ks++) {
            const uint32_t col = (uint32_t)(ks * 32 + khb) ^ xorv;
            uint32_t bf[2][4];
            ldsm4(bf[0], base + G1_B + brow + col);
            ldsm4(bf[1], base + G1_B + brow + 16 * 128 + col);
            uint32_t ah[2][4], al[2][4];
#pragma unroll
            for (int mt = 0; mt < 2; mt++) {
                ldsm4(ah[mt], base + G1_AHI + arow + mt * 16 * 128 + col);
                ldsm4(al[mt], base + G1_ALO + arow + mt * 16 * 128 + col);
            }
#pragma unroll
            for (int mt = 0; mt < 2; mt++)
#pragma unroll
                for (int nt = 0; nt < 4; nt++) {
                    uint32_t b0 = bf[nt >> 1][nt & 1], b1 = bf[nt >> 1][2 + (nt & 1)];
                    mma16816(acc[mt][nt], ah[mt], b0, b1);
                    mma16816(acc[mt][nt], al[mt], b0, b1);
                }
        }
        __syncthreads();
        if (kc + 2 < 8) { load_stage(kc + 2); CP_COMMIT(); }
    }

    // epilogue: +bias, relu, fp16 store
#pragma unroll
    for (int mt = 0; mt < 2; mt++) {
        const int row = m0 + wm * 32 + mt * 16 + (lane >> 2);
#pragma unroll
        for (int nt = 0; nt < 4; nt++) {
            const int col = n0 + wn * 32 + nt * 8 + (lane & 3) * 2;
            float2 bb = *(const float2*)&bias[col];
            __half2 h0 = __floats2half2_rn(fmaxf(acc[mt][nt][0] + bb.x, 0.f),
                                           fmaxf(acc[mt][nt][1] + bb.y, 0.f));
            __half2 h1 = __floats2half2_rn(fmaxf(acc[mt][nt][2] + bb.x, 0.f),
                                           fmaxf(acc[mt][nt][3] + bb.y, 0.f));
            *(__half2*)&g_edge_hi[(size_t)row * 1024 + col] = h0;
            *(__half2*)&g_edge_hi[(size_t)(row + 8) * 1024 + col] = h1;
        }
    }
}

// ===========================================================================
// Fused: GEMM2 (single-pass fp16) -> *union -> GEMM3 (single-pass) -> +freq
// 512 threads, M=128 rows/CTA, pool in 32 chunks of 128, K-stage 128.
// ===========================================================================
__global__ __launch_bounds__(512, 1) void k_fused_mma(
    const float* __restrict__ bcat,
    const float* __restrict__ unionf,
    const int*   __restrict__ pairs,
    const int*   __restrict__ obj_preds,
    const float* __restrict__ bctx,
    const float* __restrict__ freq,
    float*       __restrict__ out)
{
    extern __shared__ __align__(1024) char smc[];
    const uint32_t sb = smem_u32(smc);
    const int t = threadIdx.x;
    const int lane = t & 31, wid = t >> 5;
    const int wm = wid >> 2, wn = wid & 3;
    const int gm = wid >> 2, gn = wid & 3;
    const int r0 = blockIdx.x * 128;

    int* p0s = (int*)(smc + P0OFF);
    int* p1s = (int*)(smc + P1OFF);
    int* opx = (int*)(smc + OPOFF);

    if (t < 128) {
        int a = pairs[(size_t)(r0 + t) * 2 + 0];
        int b = pairs[(size_t)(r0 + t) * 2 + 1];
        p0s[t] = a; p1s[t] = b;
        opx[t] = obj_preds[a] * NOBJCLS + obj_preds[b];
    }
    __syncthreads();

    // stage loader: A [128m][128k] gathered + B [128n][128k]; g = nc*8 + kc (256 total)
    auto load_stage = [&](int g) {
        const int st = g & 1, kc = g & 7, ncn = g >> 3;
        const uint32_t base = sb + st * STAGE;
#pragma unroll
        for (int i = 0; i < 4; i++) {
            int idx = t + i * 512;                // 2048 slots
            int row = idx >> 4, j = idx & 15;
            uint32_t d = (uint32_t)row * 256 + (((uint32_t)j * 16) ^ ((uint32_t)(row & 7) << 4));
            int src = (kc < 4) ? p0s[row] : p1s[row];
            CP16(base + OFF_A + d, &g_edge_hi[(size_t)src * 1024 + kc * 128 + j * 8]);
            CP16(base + OFF_B + d, &g_wcatT[((size_t)(ncn * 128 + row)) * 1024 + kc * 128 + j * 8]);
        }
    };

    load_stage(0); CP_COMMIT();
    load_stage(1); CP_COMMIT();

    const uint32_t xorv = (lane & 7) << 4;
    const uint32_t khb  = (lane >> 4) * 16;
    const uint32_t arow = (uint32_t)(wm * 32 + (lane & 15)) * 256;   // 256B rows
    const uint32_t brow = (uint32_t)(wn * 32 + (lane & 15)) * 256;
    const uint32_t zrow = (uint32_t)(gm * 32 + (lane & 15)) * 128;   // 128B rows
    const uint32_t wrow = (uint32_t)(gn * 16 + (lane & 15)) * 128;
    const uint32_t zxor = ((lane >> 2) & 7) << 4;

    float acc3[2][2][4];
#pragma unroll
    for (int a = 0; a < 2; a++)
#pragma unroll
        for (int b = 0; b < 2; b++)
#pragma unroll
            for (int c = 0; c < 4; c++) acc3[a][b][c] = 0.f;

    for (int nc = 0; nc < 32; nc++) {
        const int n0 = nc * 128;
        float acc2[2][4][4];
#pragma unroll
        for (int a = 0; a < 2; a++)
#pragma unroll
            for (int b = 0; b < 4; b++)
#pragma unroll
                for (int c = 0; c < 4; c++) acc2[a][b][c] = 0.f;

        // ---------------- GEMM2 K loop: 8 stages of 128k ----------------
        for (int kc = 0; kc < 8; kc++) {
            const int g = nc * 8 + kc;
            if (g == 255) { WAITG(0); } else { WAITG(1); }
            __syncthreads();

            const uint32_t base = sb + (g & 1) * STAGE;
#pragma unroll
            for (int ks = 0; ks < 8; ks++) {
                const uint32_t col = (uint32_t)(ks * 32 + khb) ^ xorv;
                uint32_t bf[2][4];
                ldsm4(bf[0], base + OFF_B + brow + col);
                ldsm4(bf[1], base + OFF_B + brow + 16 * 256 + col);
                uint32_t ah[2][4];
#pragma unroll
                for (int mt = 0; mt < 2; mt++)
                    ldsm4(ah[mt], base + OFF_A + arow + mt * 16 * 256 + col);
#pragma unroll
                for (int mt = 0; mt < 2; mt++)
#pragma unroll
                    for (int nt = 0; nt < 4; nt++)
                        mma16816(acc2[mt][nt], ah[mt],
                                 bf[nt >> 1][nt & 1], bf[nt >> 1][2 + (nt & 1)]);
            }
            __syncthreads();
            if (g + 2 < 256) { load_stage(g + 2); CP_COMMIT(); }
        }

        // ---------------- epilogue: z = (acc2 + bcat) * union -> smem fp16 ----------------
#pragma unroll
        for (int mt = 0; mt < 2; mt++) {
            const int mloc = wm * 32 + mt * 16 + (lane >> 2);
#pragma unroll
            for (int nt = 0; nt < 4; nt++) {
                const int nl = wn * 32 + nt * 8 + (lane & 3) * 2;
                const int sub = nl >> 6, kl = nl & 63;
                float2 bb = *(const float2*)&bcat[n0 + nl];
                float2 u0 = *(const float2*)&unionf[(size_t)(r0 + mloc) * POOL + n0 + nl];
                float2 u1 = *(const float2*)&unionf[(size_t)(r0 + mloc + 8) * POOL + n0 + nl];
                uint32_t h01 = packh((acc2[mt][nt][0] + bb.x) * u0.x,
                                     (acc2[mt][nt][1] + bb.y) * u0.y);
                uint32_t h23 = packh((acc2[mt][nt][2] + bb.x) * u1.x,
                                     (acc2[mt][nt][3] + bb.y) * u1.y);
                uint32_t d0 = (uint32_t)mloc * 128 + (((uint32_t)kl * 2) ^ zxor);
                *(uint32_t*)(smc + ZOFF + sub * 16384 + d0) = h01;
                *(uint32_t*)(smc + ZOFF + sub * 16384 + d0 + 8 * 128) = h23;
            }
        }
        // W_ctx tiles: 2 subs of [64 cls][64 k]
#pragma unroll
        for (int i = 0; i < 2; i++) {
            int idx = t + i * 512;               // 1024 slots
            int s = idx >> 9, rem = idx & 511, row = rem >> 3, j = rem & 7;
            uint32_t d = (uint32_t)(WCOFF + s * 8192) + (uint32_t)row * 128 +
                         (((uint32_t)j * 16) ^ ((uint32_t)(row & 7) << 4));
            CP16(sb + d, &g_wctxT[(size_t)row * POOL + n0 + s * 64 + j * 8]);
        }
        CP_COMMIT();
        WAITG(0);
        __syncthreads();

        // ---------------- GEMM3 accumulate (single pass) ----------------
#pragma unroll
        for (int s = 0; s < 2; s++) {
#pragma unroll
            for (int ks = 0; ks < 4; ks++) {
                const uint32_t col = (uint32_t)(ks * 32 + khb) ^ xorv;
                uint32_t bf[4];
                ldsm4(bf, sb + WCOFF + s * 8192 + wrow + col);
                uint32_t zh[2][4];
#pragma unroll
                for (int mt = 0; mt < 2; mt++)
                    ldsm4(zh[mt], sb + ZOFF + s * 16384 + zrow + mt * 16 * 128 + col);
#pragma unroll
                for (int mt = 0; mt < 2; mt++)
#pragma unroll
                    for (int nt = 0; nt < 2; nt++)
                        mma16816(acc3[mt][nt], zh[mt], bf[nt], bf[2 + nt]);
            }
        }
        __syncthreads();   // protect z/WC before next chunk's epilogue
    }

    // ---------------- final: out = acc3 + bctx + freq ----------------
#pragma unroll
    for (int mt = 0; mt < 2; mt++) {
        const int m0l = gm * 32 + mt * 16 + (lane >> 2);
#pragma unroll
        for (int r = 0; r < 2; r++) {
            const int m = m0l + r * 8;
            const int pidx = opx[m];
            const float* fr = &freq[(size_t)pidx * NRELCLS];
            float* op = &out[(size_t)(r0 + m) * NRELCLS];
#pragma unroll
            for (int nt = 0; nt < 2; nt++) {
                const int c = gn * 16 + nt * 8 + (lane & 3) * 2;
                if (c < NRELCLS)
                    op[c] = acc3[mt][nt][r * 2 + 0] + bctx[c] + fr[c];
                if (c + 1 < NRELCLS)
                    op[c + 1] = acc3[mt][nt][r * 2 + 1] + bctx[c + 1] + fr[c + 1];
            }
        }
    }
}

// ===========================================================================
extern "C" void kernel_launch(void* const* d_in, const int* in_sizes, int n_in,
                              void* d_out, int out_size)
{
    const float* edge_ctx   = (const float*)d_in[0];
    const float* unionf     = (const float*)d_in[1];
    const int*   pairs      = (const int*)  d_in[2];
    const int*   obj_preds  = (const int*)  d_in[3];
    const float* W_post_emb = (const float*)d_in[4];
    const float* b_post_emb = (const float*)d_in[5];
    const float* W_post_cat = (const float*)d_in[6];
    const float* b_post_cat = (const float*)d_in[7];
    const float* W_ctx      = (const float*)d_in[8];
    const float* b_ctx      = (const float*)d_in[9];
    const float* freq       = (const float*)d_in[10];
    float* out = (float*)d_out;

    cudaFuncSetAttribute(k_gemm1_mma, cudaFuncAttributeMaxDynamicSharedMemorySize, SMEM_G1);
    cudaFuncSetAttribute(k_fused_mma, cudaFuncAttributeMaxDynamicSharedMemorySize, SMEM_FUSED);

    k_ec_prep<<<(NOBJ * HID) / 256, 256>>>(edge_ctx);
    k_wemb_prep<<<dim3(1024 / 32, HID / 32), dim3(32, 8)>>>(W_post_emb);
    k_wcat_prep<<<dim3(POOL / 32, 1024 / 32), dim3(32, 8)>>>(W_post_cat);
    k_wctx_prep<<<(64 * POOL) / 256, 256>>>(W_ctx);
    k_gemm1_mma<<<dim3(NOBJ / 128, 1024 / 128), 512, SMEM_G1>>>(b_post_emb);
    k_fused_mma<<<NREL / 128, 512, SMEM_FUSED>>>(b_post_cat, unionf, pairs, obj_preds,
                                                 b_ctx, freq, out);
}

// round 6
// speedup vs baseline: 6.6095x; 1.0475x over previous
#include <cuda_runtime.h>
#include <cuda_fp16.h>
#include <cstdint>

#define HID      512
#define NOBJ     8192
#define NREL     32768
#define POOL     4096
#define NRELCLS  51
#define NOBJCLS  151

// -------------------- device scratch --------------------
__device__ __align__(256) __half g_edge_hi[NOBJ * 1024];
__device__ __align__(256) __half g_wcatT[POOL * 1024];   // [n][k] fp16
__device__ __align__(256) __half g_wctxT[64 * POOL];     // [cls pad64][k] fp16
__device__ __align__(256) __half g_ec_hi[NOBJ * HID];    // edge_ctx split
__device__ __align__(256) __half g_ec_lo[NOBJ * HID];
__device__ __align__(256) __half g_wembT[1024 * HID];    // [n][k] fp16

// -------------------- helpers --------------------
__device__ __forceinline__ uint32_t smem_u32(const void* p) {
    uint32_t a;
    asm("{ .reg .u64 t; cvta.to.shared.u64 t, %1; cvt.u32.u64 %0, t; }" : "=r"(a) : "l"(p));
    return a;
}
#define CP16(d, s)   asm volatile("cp.async.cg.shared.global [%0], [%1], 16;" :: "r"(d), "l"(s) : "memory")
#define CP_COMMIT()  asm volatile("cp.async.commit_group;" ::: "memory")
#define WAITG(n)     asm volatile("cp.async.wait_group %0;" :: "n"(n) : "memory")

__device__ __forceinline__ void ldsm4(uint32_t* r, uint32_t a) {
    asm volatile("ldmatrix.sync.aligned.m8n8.x4.shared.b16 {%0,%1,%2,%3}, [%4];"
                 : "=r"(r[0]), "=r"(r[1]), "=r"(r[2]), "=r"(r[3]) : "r"(a));
}
__device__ __forceinline__ void mma16816(float* d, const uint32_t* a, uint32_t b0, uint32_t b1) {
    asm volatile(
        "mma.sync.aligned.m16n8k16.row.col.f32.f16.f16.f32 "
        "{%0,%1,%2,%3}, {%4,%5,%6,%7}, {%8,%9}, {%0,%1,%2,%3};"
        : "+f"(d[0]), "+f"(d[1]), "+f"(d[2]), "+f"(d[3])
        : "r"(a[0]), "r"(a[1]), "r"(a[2]), "r"(a[3]), "r"(b0), "r"(b1));
}
__device__ __forceinline__ uint32_t packh(float e0, float e1) {
    uint32_t r;
    asm("cvt.rn.f16x2.f32 %0, %1, %2;" : "=r"(r) : "f"(e1), "f"(e0));  // low = e0
    return r;
}

// -------------------- smem layout: fused kernel (bytes) --------------------
#define STAGE    49152           // A [128m][64k] 16KB + B [256n][64k] 32KB
#define OFF_A    0
#define OFF_B    16384
#define ZOFF     98304           // 4 x 16384: z [128m][64k] sub-tiles
#define WCOFF    163840          // 4 x 8192: Wctx [64cls][64k] sub-tiles
#define P0OFF    196608
#define P1OFF    197120
#define OPOFF    197632
#define SMEM_FUSED 198144

// -------------------- smem layout: gemm1 kernel --------------------
#define G1STAGE  49152           // Ahi 16K + Alo 16K + B 16K
#define G1_AHI   0
#define G1_ALO   16384
#define G1_B     32768
#define SMEM_G1  98304

// ===========================================================================
// Preps
// ===========================================================================
__global__ void k_ec_prep(const float* __restrict__ src) {
    int idx = blockIdx.x * 256 + threadIdx.x;
    float v = src[idx];
    __half h = __float2half_rn(v);
    g_ec_hi[idx] = h;
    g_ec_lo[idx] = __float2half_rn(v - __half2float(h));
}

__global__ void k_wemb_prep(const float* __restrict__ src) {  // [512][1024] -> [1024][512]
    __shared__ float tile[32][33];
    int tx = threadIdx.x, ty = threadIdx.y;
    int c0 = blockIdx.x * 32, r0 = blockIdx.y * 32;
    for (int i = ty; i < 32; i += 8)
        tile[i][tx] = src[(size_t)(r0 + i) * 1024 + c0 + tx];
    __syncthreads();
    for (int i = ty; i < 32; i += 8)
        g_wembT[(size_t)(c0 + i) * HID + r0 + tx] = __float2half_rn(tile[tx][i]);
}

__global__ void k_wcat_prep(const float* __restrict__ src) {  // [1024][4096] -> [4096][1024]
    __shared__ float tile[32][33];
    int tx = threadIdx.x, ty = threadIdx.y;
    int c0 = blockIdx.x * 32, r0 = blockIdx.y * 32;
    for (int i = ty; i < 32; i += 8)
        tile[i][tx] = src[(size_t)(r0 + i) * POOL + c0 + tx];
    __syncthreads();
    for (int i = ty; i < 32; i += 8)
        g_wcatT[(size_t)(c0 + i) * 1024 + r0 + tx] = __float2half_rn(tile[tx][i]);
}

__global__ void k_wctx_prep(const float* __restrict__ Wctx) {
    int idx = blockIdx.x * 256 + threadIdx.x;   // 64*4096
    int c = idx >> 12, k = idx & 4095;
    float v = (c < NRELCLS) ? Wctx[(size_t)k * NRELCLS + c] : 0.f;
    g_wctxT[idx] = __float2half_rn(v);
}

// ===========================================================================
// GEMM1 (mma, 2-pass A): edge_rep = relu(edge_ctx @ W_post_emb + b) -> fp16
// ===========================================================================
__global__ __launch_bounds__(512, 1) void k_gemm1_mma(const float* __restrict__ bias)
{
    extern __shared__ __align__(1024) char smc[];
    const uint32_t sb = smem_u32(smc);
    const int t = threadIdx.x;
    const int lane = t & 31, wid = t >> 5;
    const int wm = wid >> 2, wn = wid & 3;
    const int m0 = blockIdx.x * 128, n0 = blockIdx.y * 128;

    auto load_stage = [&](int kc) {
        const uint32_t base = sb + (kc & 1) * G1STAGE;
#pragma unroll
        for (int i = 0; i < 2; i++) {
            int idx = t + i * 512;
            int row = idx >> 3, j = idx & 7;
            uint32_t d = (uint32_t)row * 128 + (((uint32_t)j * 16) ^ ((uint32_t)(row & 7) << 4));
            CP16(base + G1_AHI + d, &g_ec_hi[(size_t)(m0 + row) * HID + kc * 64 + j * 8]);
            CP16(base + G1_ALO + d, &g_ec_lo[(size_t)(m0 + row) * HID + kc * 64 + j * 8]);
            CP16(base + G1_B   + d, &g_wembT[(size_t)(n0 + row) * HID + kc * 64 + j * 8]);
        }
    };
    load_stage(0); CP_COMMIT();
    load_stage(1); CP_COMMIT();

    const uint32_t xorv = (lane & 7) << 4;
    const uint32_t khb  = (lane >> 4) * 16;
    const uint32_t arow = (uint32_t)(wm * 32 + (lane & 15)) * 128;
    const uint32_t brow = (uint32_t)(wn * 32 + (lane & 15)) * 128;

    float acc[2][4][4];
#pragma unroll
    for (int a = 0; a < 2; a++)
#pragma unroll
        for (int b = 0; b < 4; b++)
#pragma unroll
            for (int c = 0; c < 4; c++) acc[a][b][c] = 0.f;

    for (int kc = 0; kc < 8; kc++) {
        if (kc == 7) { WAITG(0); } else { WAITG(1); }
        __syncthreads();
        const uint32_t base = sb + (kc & 1) * G1STAGE;
#pragma unroll
        for (int ks = 0; ks < 4; ks++) {
            const uint32_t col = (uint32_t)(ks * 32 + khb) ^ xorv;
            uint32_t bf[2][4];
            ldsm4(bf[0], base + G1_B + brow + col);
            ldsm4(bf[1], base + G1_B + brow + 16 * 128 + col);
            uint32_t ah[2][4], al[2][4];
#pragma unroll
            for (int mt = 0; mt < 2; mt++) {
                ldsm4(ah[mt], base + G1_AHI + arow + mt * 16 * 128 + col);
                ldsm4(al[mt], base + G1_ALO + arow + mt * 16 * 128 + col);
            }
#pragma unroll
            for (int mt = 0; mt < 2; mt++)
#pragma unroll
                for (int nt = 0; nt < 4; nt++) {
                    uint32_t b0 = bf[nt >> 1][nt & 1], b1 = bf[nt >> 1][2 + (nt & 1)];
                    mma16816(acc[mt][nt], ah[mt], b0, b1);
                    mma16816(acc[mt][nt], al[mt], b0, b1);
                }
        }
        __syncthreads();
        if (kc + 2 < 8) { load_stage(kc + 2); CP_COMMIT(); }
    }

#pragma unroll
    for (int mt = 0; mt < 2; mt++) {
        const int row = m0 + wm * 32 + mt * 16 + (lane >> 2);
#pragma unroll
        for (int nt = 0; nt < 4; nt++) {
            const int col = n0 + wn * 32 + nt * 8 + (lane & 3) * 2;
            float2 bb = *(const float2*)&bias[col];
            __half2 h0 = __floats2half2_rn(fmaxf(acc[mt][nt][0] + bb.x, 0.f),
                                           fmaxf(acc[mt][nt][1] + bb.y, 0.f));
            __half2 h1 = __floats2half2_rn(fmaxf(acc[mt][nt][2] + bb.x, 0.f),
                                           fmaxf(acc[mt][nt][3] + bb.y, 0.f));
            *(__half2*)&g_edge_hi[(size_t)row * 1024 + col] = h0;
            *(__half2*)&g_edge_hi[(size_t)(row + 8) * 1024 + col] = h1;
        }
    }
}

// ===========================================================================
// Fused: GEMM2 -> *union -> GEMM3 -> +freq
// 256 threads (8 warps). CTA tile M128 x N256. Warp tile GEMM2: 64x64 (2x4).
// k-stage 64, 2-stage cp.async. 16 pool chunks of 256.
// ===========================================================================
__global__ __launch_bounds__(256, 1) void k_fused_mma(
    const float* __restrict__ bcat,
    const float* __restrict__ unionf,
    const int*   __restrict__ pairs,
    const int*   __restrict__ obj_preds,
    const float* __restrict__ bctx,
    const float* __restrict__ freq,
    float*       __restrict__ out)
{
    extern __shared__ __align__(1024) char smc[];
    const uint32_t sb = smem_u32(smc);
    const int t = threadIdx.x;
    const int lane = t & 31, wid = t >> 5;
    const int wm = wid >> 2, wn = wid & 3;   // GEMM2: 2m x 4n, warp tile 64x64
    const int gm = wid >> 1, gn = wid & 1;   // GEMM3: 4m x 2n, warp tile 32m x 32cls
    const int r0 = blockIdx.x * 128;

    int* p0s = (int*)(smc + P0OFF);
    int* p1s = (int*)(smc + P1OFF);
    int* opx = (int*)(smc + OPOFF);

    if (t < 128) {
        int a = pairs[(size_t)(r0 + t) * 2 + 0];
        int b = pairs[(size_t)(r0 + t) * 2 + 1];
        p0s[t] = a; p1s[t] = b;
        opx[t] = obj_preds[a] * NOBJCLS + obj_preds[b];
    }
    __syncthreads();

    // stage loader: A [128m][64k] gathered + B [256n][64k]; g = nc*16 + kst (256 total)
    auto load_stage = [&](int g) {
        const int st = g & 1, kc = g & 15, ncn = g >> 4;
        const uint32_t base = sb + st * STAGE;
#pragma unroll
        for (int i = 0; i < 4; i++) {           // A: 1024 slots
            int idx = t + i * 256;
            int row = idx >> 3, j = idx & 7;
            uint32_t d = (uint32_t)row * 128 + (((uint32_t)j * 16) ^ ((uint32_t)(row & 7) << 4));
            int src = (kc < 8) ? p0s[row] : p1s[row];
            CP16(base + OFF_A + d, &g_edge_hi[(size_t)src * 1024 + kc * 64 + j * 8]);
        }
#pragma unroll
        for (int i = 0; i < 8; i++) {           // B: 2048 slots
            int idx = t + i * 256;
            int row = idx >> 3, j = idx & 7;
            uint32_t d = (uint32_t)row * 128 + (((uint32_t)j * 16) ^ ((uint32_t)(row & 7) << 4));
            CP16(base + OFF_B + d, &g_wcatT[((size_t)(ncn * 256 + row)) * 1024 + kc * 64 + j * 8]);
        }
    };

    load_stage(0); CP_COMMIT();
    load_stage(1); CP_COMMIT();

    const uint32_t xorv = (lane & 7) << 4;
    const uint32_t khb  = (lane >> 4) * 16;
    const uint32_t arow = (uint32_t)(wm * 64 + (lane & 15)) * 128;
    const uint32_t brow = (uint32_t)(wn * 64 + (lane & 15)) * 128;
    const uint32_t zrow = (uint32_t)(gm * 32 + (lane & 15)) * 128;
    const uint32_t wrow = (uint32_t)(gn * 32 + (lane & 15)) * 128;
    const uint32_t zxor = ((lane >> 2) & 7) << 4;

    float acc3[2][4][4];
#pragma unroll
    for (int a = 0; a < 2; a++)
#pragma unroll
        for (int b = 0; b < 4; b++)
#pragma unroll
            for (int c = 0; c < 4; c++) acc3[a][b][c] = 0.f;

    for (int nc = 0; nc < 16; nc++) {
        const int n0 = nc * 256;
        float acc2[4][8][4];
#pragma unroll
        for (int a = 0; a < 4; a++)
#pragma unroll
            for (int b = 0; b < 8; b++)
#pragma unroll
                for (int c = 0; c < 4; c++) acc2[a][b][c] = 0.f;

        // ---------------- GEMM2 K loop: 16 stages of 64k ----------------
        for (int kst = 0; kst < 16; kst++) {
            const int g = nc * 16 + kst;
            if (g == 255) { WAITG(0); } else { WAITG(1); }
            __syncthreads();

            const uint32_t base = sb + (g & 1) * STAGE;
#pragma unroll
            for (int ks = 0; ks < 4; ks++) {
                const uint32_t col = (uint32_t)(ks * 32 + khb) ^ xorv;
                uint32_t bf[4][4];
#pragma unroll
                for (int q = 0; q < 4; q++)
                    ldsm4(bf[q], base + OFF_B + brow + q * 16 * 128 + col);
                uint32_t ah[4][4];
#pragma unroll
                for (int mt = 0; mt < 4; mt++)
                    ldsm4(ah[mt], base + OFF_A + arow + mt * 16 * 128 + col);
#pragma unroll
                for (int mt = 0; mt < 4; mt++)
#pragma unroll
                    for (int nt = 0; nt < 8; nt++)
                        mma16816(acc2[mt][nt], ah[mt],
                                 bf[nt >> 1][nt & 1], bf[nt >> 1][2 + (nt & 1)]);
            }
            __syncthreads();
            if (g + 2 < 256) { load_stage(g + 2); CP_COMMIT(); }
        }

        // ---------------- epilogue: z = (acc2 + bcat) * union -> smem fp16 ----------------
#pragma unroll
        for (int mt = 0; mt < 4; mt++) {
            const int mloc = wm * 64 + mt * 16 + (lane >> 2);
#pragma unroll
            for (int nt = 0; nt < 8; nt++) {
                const int nl = wn * 64 + nt * 8 + (lane & 3) * 2;
                const int sub = nl >> 6, kl = nl & 63;
                float2 bb = *(const float2*)&bcat[n0 + nl];
                float2 u0 = *(const float2*)&unionf[(size_t)(r0 + mloc) * POOL + n0 + nl];
                float2 u1 = *(const float2*)&unionf[(size_t)(r0 + mloc + 8) * POOL + n0 + nl];
                uint32_t h01 = packh((acc2[mt][nt][0] + bb.x) * u0.x,
                                     (acc2[mt][nt][1] + bb.y) * u0.y);
                uint32_t h23 = packh((acc2[mt][nt][2] + bb.x) * u1.x,
                                     (acc2[mt][nt][3] + bb.y) * u1.y);
                uint32_t d0 = (uint32_t)mloc * 128 + (((uint32_t)kl * 2) ^ zxor);
                *(uint32_t*)(smc + ZOFF + sub * 16384 + d0) = h01;
                *(uint32_t*)(smc + ZOFF + sub * 16384 + d0 + 8 * 128) = h23;
            }
        }
        // W_ctx tiles: 4 subs of [64 cls][64 k]
#pragma unroll
        for (int i = 0; i < 8; i++) {
            int idx = t + i * 256;               // 2048 slots
            int s = idx >> 9, rem = idx & 511, row = rem >> 3, j = rem & 7;
            uint32_t d = (uint32_t)(WCOFF + s * 8192) + (uint32_t)row * 128 +
                         (((uint32_t)j * 16) ^ ((uint32_t)(row & 7) << 4));
            CP16(sb + d, &g_wctxT[(size_t)row * POOL + n0 + s * 64 + j * 8]);
        }
        CP_COMMIT();
        WAITG(0);
        __syncthreads();

        // ---------------- GEMM3 accumulate ----------------
#pragma unroll
        for (int s = 0; s < 4; s++) {
#pragma unroll
            for (int ks = 0; ks < 4; ks++) {
                const uint32_t col = (uint32_t)(ks * 32 + khb) ^ xorv;
                uint32_t bf[2][4];
                ldsm4(bf[0], sb + WCOFF + s * 8192 + wrow + col);
                ldsm4(bf[1], sb + WCOFF + s * 8192 + wrow + 16 * 128 + col);
                uint32_t zf[2][4];
#pragma unroll
                for (int mt = 0; mt < 2; mt++)
                    ldsm4(zf[mt], sb + ZOFF + s * 16384 + zrow + mt * 16 * 128 + col);
#pragma unroll
                for (int mt = 0; mt < 2; mt++)
#pragma unroll
                    for (int nt = 0; nt < 4; nt++)
                        mma16816(acc3[mt][nt], zf[mt],
                                 bf[nt >> 1][nt & 1], bf[nt >> 1][2 + (nt & 1)]);
            }
        }
        __syncthreads();   // protect z/WC before next chunk's epilogue
    }

    // ---------------- final: out = acc3 + bctx + freq ----------------
#pragma unroll
    for (int mt = 0; mt < 2; mt++) {
        const int m0l = gm * 32 + mt * 16 + (lane >> 2);
#pragma unroll
        for (int r = 0; r < 2; r++) {
            const int m = m0l + r * 8;
            const int pidx = opx[m];
            const float* fr = &freq[(size_t)pidx * NRELCLS];
            float* op = &out[(size_t)(r0 + m) * NRELCLS];
#pragma unroll
            for (int nt = 0; nt < 4; nt++) {
                const int c = gn * 32 + nt * 8 + (lane & 3) * 2;
                if (c < NRELCLS)
                    op[c] = acc3[mt][nt][r * 2 + 0] + bctx[c] + fr[c];
                if (c + 1 < NRELCLS)
                    op[c + 1] = acc3[mt][nt][r * 2 + 1] + bctx[c + 1] + fr[c + 1];
            }
        }
    }
}

// ===========================================================================
extern "C" void kernel_launch(void* const* d_in, const int* in_sizes, int n_in,
                              void* d_out, int out_size)
{
    const float* edge_ctx   = (const float*)d_in[0];
    const float* unionf     = (const float*)d_in[1];
    const int*   pairs      = (const int*)  d_in[2];
    const int*   obj_preds  = (const int*)  d_in[3];
    const float* W_post_emb = (const float*)d_in[4];
    const float* b_post_emb = (const float*)d_in[5];
    const float* W_post_cat = (const float*)d_in[6];
    const float* b_post_cat = (const float*)d_in[7];
    const float* W_ctx      = (const float*)d_in[8];
    const float* b_ctx      = (const float*)d_in[9];
    const float* freq       = (const float*)d_in[10];
    float* out = (float*)d_out;

    cudaFuncSetAttribute(k_gemm1_mma, cudaFuncAttributeMaxDynamicSharedMemorySize, SMEM_G1);
    cudaFuncSetAttribute(k_fused_mma, cudaFuncAttributeMaxDynamicSharedMemorySize, SMEM_FUSED);

    k_ec_prep<<<(NOBJ * HID) / 256, 256>>>(edge_ctx);
    k_wemb_prep<<<dim3(1024 / 32, HID / 32), dim3(32, 8)>>>(W_post_emb);
    k_wcat_prep<<<dim3(POOL / 32, 1024 / 32), dim3(32, 8)>>>(W_post_cat);
    k_wctx_prep<<<(64 * POOL) / 256, 256>>>(W_ctx);
    k_gemm1_mma<<<dim3(NOBJ / 128, 1024 / 128), 512, SMEM_G1>>>(b_post_emb);
    k_fused_mma<<<NREL / 128, 256, SMEM_FUSED>>>(b_post_cat, unionf, pairs, obj_preds,
                                                 b_ctx, freq, out);
}